// round 1
// baseline (speedup 1.0000x reference)
#include <cuda_runtime.h>
#include <cuda_bf16.h>
#include <math.h>

// Problem dims
#define BB   256
#define SS   200
#define FF   10
#define EE   128
#define HH   256
#define G4H  1024   // 4*H
#define TT   100
#define P1_  512
#define P2_  128
#define MT   (BB*TT)   // 25600

// ---------------- scratch (static device globals; no runtime alloc) -------
__device__ float g_e[BB*SS*EE];          // 6.55M  (26 MB)
__device__ float g_xproj[(size_t)BB*SS*G4H]; // 52.4M (210 MB)
__device__ float g_WihT[EE*G4H];         // 128x1024
__device__ float g_WhhT[HH*G4H];         // 256x1024
__device__ float g_bsum[G4H];
__device__ float g_hN[BB*HH];
__device__ float g_cN[BB*HH];
__device__ float g_hproj[BB*G4H];
__device__ float g_htgt[(size_t)MT*HH];  // 26 MB
__device__ float g_z1[(size_t)MT*P1_];   // 52 MB
__device__ float g_z2[(size_t)MT*P2_];   // 13 MB

__device__ __forceinline__ float sigm(float x) { return 1.0f / (1.0f + expf(-x)); }

// ---------------- prep: transpose W_ih, W_hh to K-major; combine biases ----
__global__ void prep_kernel(const float* __restrict__ W_ih,
                            const float* __restrict__ W_hh,
                            const float* __restrict__ b_ih,
                            const float* __restrict__ b_hh) {
    int idx = blockIdx.x * blockDim.x + threadIdx.x;
    if (idx < EE * G4H) {          // WihT[k*1024 + j] = W_ih[j*128 + k]
        int k = idx >> 10, j = idx & 1023;
        g_WihT[idx] = W_ih[j * EE + k];
    }
    if (idx < HH * G4H) {          // WhhT[k*1024 + j] = W_hh[j*256 + k]
        int k = idx >> 10, j = idx & 1023;
        g_WhhT[idx] = W_hh[j * HH + k];
    }
    if (idx < G4H) g_bsum[idx] = b_ih[idx] + b_hh[idx];
}

// ---------------- embedding gather + mean over F -------------------------
__global__ void gather_mean_kernel(const int* __restrict__ x,
                                   const float* __restrict__ emb) {
    int bs = blockIdx.x;           // 0..B*S-1
    int k  = threadIdx.x;          // 0..127
    const int* xi = x + bs * FF;
    float s = 0.f;
#pragma unroll
    for (int f = 0; f < FF; f++) {
        s += emb[(size_t)xi[f] * EE + k];
    }
    g_e[(size_t)bs * EE + k] = s * 0.1f;
}

// ---------------- generic fp32 SGEMM: C = act(A@B + bias) ----------------
// A: MxK row-major, B: KxN row-major, C: MxN. Requires M%64==0, N%64==0,
// K%16==0 (all call sites satisfy this).
#define BM 64
#define BN 64
#define BKK 16
__global__ __launch_bounds__(256)
void sgemm_kernel(const float* __restrict__ A, const float* __restrict__ B,
                  float* __restrict__ C, const float* __restrict__ bias,
                  int M, int N, int K, int relu) {
    __shared__ float As[BKK][BM + 4];
    __shared__ float Bs[BKK][BN];
    int tid = threadIdx.x;
    int m0 = blockIdx.y * BM;
    int n0 = blockIdx.x * BN;
    int tx = tid & 15, ty = tid >> 4;

    int arow = tid >> 2;            // 0..63
    int acol = (tid & 3) * 4;       // 0,4,8,12
    int brow = tid >> 4;            // 0..15
    int bcol = (tid & 15) * 4;      // 0..60

    float acc[4][4] = {};
    for (int k0 = 0; k0 < K; k0 += BKK) {
        float4 av = *(const float4*)&A[(size_t)(m0 + arow) * K + k0 + acol];
        As[acol + 0][arow] = av.x;
        As[acol + 1][arow] = av.y;
        As[acol + 2][arow] = av.z;
        As[acol + 3][arow] = av.w;
        float4 bv = *(const float4*)&B[(size_t)(k0 + brow) * N + n0 + bcol];
        *(float4*)&Bs[brow][bcol] = bv;
        __syncthreads();
#pragma unroll
        for (int kk = 0; kk < BKK; kk++) {
            float a[4], b[4];
            *(float4*)a = *(const float4*)&As[kk][ty * 4];
            *(float4*)b = *(const float4*)&Bs[kk][tx * 4];
#pragma unroll
            for (int i = 0; i < 4; i++)
#pragma unroll
                for (int j = 0; j < 4; j++)
                    acc[i][j] += a[i] * b[j];
        }
        __syncthreads();
    }
#pragma unroll
    for (int i = 0; i < 4; i++) {
        int m = m0 + ty * 4 + i;
#pragma unroll
        for (int j = 0; j < 4; j++) {
            int n = n0 + tx * 4 + j;
            float v = acc[i][j];
            if (bias) v += bias[n];
            if (relu) v = fmaxf(v, 0.f);
            C[(size_t)m * N + n] = v;
        }
    }
}

// ---------------- LSTM recurrence over hist (100 steps) ------------------
// One CTA handles 4 batch rows; no inter-CTA dependence. h in SMEM, c in regs.
#define LROWS 4
__global__ __launch_bounds__(256)
void lstm_kernel(const float* __restrict__ xproj,
                 const float* __restrict__ WhhT,
                 float* __restrict__ hN, float* __restrict__ cN) {
    int j = threadIdx.x;                 // output h-column 0..255
    int b0 = blockIdx.x * LROWS;
    __shared__ float sh_h[LROWS][HH];
    float c[LROWS];
#pragma unroll
    for (int r = 0; r < LROWS; r++) { sh_h[r][j] = 0.f; c[r] = 0.f; }
    __syncthreads();

    for (int t = 0; t < TT; t++) {
        float ai[LROWS], af[LROWS], ag[LROWS], ao[LROWS];
#pragma unroll
        for (int r = 0; r < LROWS; r++) {
            size_t base = ((size_t)(b0 + r) * SS + t) * G4H + j;
            ai[r] = xproj[base];
            af[r] = xproj[base + 256];
            ag[r] = xproj[base + 512];
            ao[r] = xproj[base + 768];
        }
#pragma unroll 4
        for (int k = 0; k < HH; k++) {
            const float* w = &WhhT[(size_t)k * G4H + j];
            float wi = w[0], wf = w[256], wg = w[512], wo = w[768];
#pragma unroll
            for (int r = 0; r < LROWS; r++) {
                float hk = sh_h[r][k];
                ai[r] = fmaf(hk, wi, ai[r]);
                af[r] = fmaf(hk, wf, af[r]);
                ag[r] = fmaf(hk, wg, ag[r]);
                ao[r] = fmaf(hk, wo, ao[r]);
            }
        }
        float hnew[LROWS];
#pragma unroll
        for (int r = 0; r < LROWS; r++) {
            float cc = sigm(af[r]) * c[r] + sigm(ai[r]) * tanhf(ag[r]);
            c[r] = cc;
            hnew[r] = sigm(ao[r]) * tanhf(cc);
        }
        __syncthreads();
#pragma unroll
        for (int r = 0; r < LROWS; r++) sh_h[r][j] = hnew[r];
        __syncthreads();
    }
#pragma unroll
    for (int r = 0; r < LROWS; r++) {
        hN[(b0 + r) * HH + j] = sh_h[r][j];
        cN[(b0 + r) * HH + j] = c[r];
    }
}

// ---------------- tgt single-step LSTM (non-recurrent, parallel) ---------
__global__ __launch_bounds__(256)
void tgt_kernel(const float* __restrict__ xproj,
                const float* __restrict__ hproj,
                const float* __restrict__ cN) {
    int bt = blockIdx.x;            // 0..25599  (m = b*T + t)
    int j  = threadIdx.x;
    int b = bt / TT, t = bt % TT;
    size_t base = ((size_t)b * SS + TT + t) * G4H + j;
    const float* hp = hproj + (size_t)b * G4H + j;
    float gi = xproj[base]       + hp[0];
    float gf = xproj[base + 256] + hp[256];
    float gg = xproj[base + 512] + hp[512];
    float go = xproj[base + 768] + hp[768];
    float cc = sigm(gf) * cN[b * HH + j] + sigm(gi) * tanhf(gg);
    g_htgt[(size_t)bt * HH + j] = sigm(go) * tanhf(cc);
}

// ---------------- final layer: out = sigmoid(z2 @ W3 + b3) ---------------
__global__ __launch_bounds__(128)
void final_kernel(const float* __restrict__ z2, const float* __restrict__ W3,
                  const float* __restrict__ b3, float* __restrict__ out) {
    int warp = threadIdx.x >> 5, lane = threadIdx.x & 31;
    int m = blockIdx.x * 4 + warp;
    if (m >= MT) return;
    const float* zr = z2 + (size_t)m * P2_;
    float s = 0.f;
#pragma unroll
    for (int q = 0; q < 4; q++) s = fmaf(zr[lane + q * 32], W3[lane + q * 32], s);
#pragma unroll
    for (int off = 16; off; off >>= 1) s += __shfl_xor_sync(0xFFFFFFFFu, s, off);
    if (lane == 0) out[m] = 1.f / (1.f + expf(-(s + b3[0])));
}

// ---------------- launch --------------------------------------------------
extern "C" void kernel_launch(void* const* d_in, const int* in_sizes, int n_in,
                              void* d_out, int out_size) {
    const int*   x    = (const int*)  d_in[0];
    const float* emb  = (const float*)d_in[1];
    const float* W_ih = (const float*)d_in[2];
    const float* W_hh = (const float*)d_in[3];
    const float* b_ih = (const float*)d_in[4];
    const float* b_hh = (const float*)d_in[5];
    const float* W1   = (const float*)d_in[6];
    const float* b1   = (const float*)d_in[7];
    const float* W2   = (const float*)d_in[8];
    const float* b2   = (const float*)d_in[9];
    const float* W3   = (const float*)d_in[10];
    const float* b3   = (const float*)d_in[11];
    float* out = (float*)d_out;

    float *e, *xproj, *WihT, *WhhT, *bsum, *hN, *cN, *hproj, *htgt, *z1, *z2;
    cudaGetSymbolAddress((void**)&e,     g_e);
    cudaGetSymbolAddress((void**)&xproj, g_xproj);
    cudaGetSymbolAddress((void**)&WihT,  g_WihT);
    cudaGetSymbolAddress((void**)&WhhT,  g_WhhT);
    cudaGetSymbolAddress((void**)&bsum,  g_bsum);
    cudaGetSymbolAddress((void**)&hN,    g_hN);
    cudaGetSymbolAddress((void**)&cN,    g_cN);
    cudaGetSymbolAddress((void**)&hproj, g_hproj);
    cudaGetSymbolAddress((void**)&htgt,  g_htgt);
    cudaGetSymbolAddress((void**)&z1,    g_z1);
    cudaGetSymbolAddress((void**)&z2,    g_z2);

    // 1) weight transposes + bias combine
    prep_kernel<<<(HH * G4H + 255) / 256, 256>>>(W_ih, W_hh, b_ih, b_hh);

    // 2) embedding gather + mean
    gather_mean_kernel<<<BB * SS, EE>>>(x, emb);

    // 3) input projection for ALL 200 timesteps: xproj = e @ W_ihT + (b_ih+b_hh)
    {
        dim3 grid(G4H / BN, (BB * SS) / BM);
        sgemm_kernel<<<grid, 256>>>(e, WihT, xproj, bsum, BB * SS, G4H, EE, 0);
    }

    // 4) LSTM recurrence over hist (t = 0..99)
    lstm_kernel<<<BB / LROWS, HH>>>(xproj, WhhT, hN, cN);

    // 5) hproj = hN @ W_hhT   (no bias; already inside xproj)
    {
        dim3 grid(G4H / BN, BB / BM);
        sgemm_kernel<<<grid, 256>>>(hN, WhhT, hproj, nullptr, BB, G4H, HH, 0);
    }

    // 6) tgt one-shot LSTM step
    tgt_kernel<<<MT, HH>>>(xproj, hproj, cN);

    // 7) MLP
    {
        dim3 grid(P1_ / BN, MT / BM);
        sgemm_kernel<<<grid, 256>>>(htgt, W1, z1, b1, MT, P1_, HH, 1);
    }
    {
        dim3 grid(P2_ / BN, MT / BM);
        sgemm_kernel<<<grid, 256>>>(z1, W2, z2, b2, MT, P2_, P1_, 1);
    }

    // 8) final dot + sigmoid
    final_kernel<<<MT / 4, 128>>>(z2, W3, b3, out);

    (void)in_sizes; (void)n_in; (void)out_size;
}